// round 1
// baseline (speedup 1.0000x reference)
#include <cuda_runtime.h>
#include <math.h>

// Problem constants (fixed shapes)
#define NN 512
#define CC 128
constexpr size_t RR = (size_t)NN * NN;        // 262144 rows (i,j)
constexpr size_t RC = RR * CC;                // 33.5M elems

// Scratch (device globals; no runtime allocation allowed)
__device__ float g_x[RC];       // layernormed input, (r, c) row-major
__device__ float g_a[RC];       // a[c][i][k]  (c-major, 512x512 per channel)
__device__ float g_b[RC];       // b[c][j][k]
__device__ float g_act2[RC];    // act2[c][i][j]
__device__ float g_mean[RR];
__device__ float g_rstd[RR];

__device__ __forceinline__ float sigm(float z) { return 1.0f / (1.0f + __expf(-z)); }

// ---------------------------------------------------------------------------
// K1: LayerNorm over last dim (C=128). One warp per row; float4 per lane.
// ---------------------------------------------------------------------------
__global__ void k_layernorm(const float* __restrict__ act,
                            const float* __restrict__ scale,
                            const float* __restrict__ offset) {
    int warp = threadIdx.x >> 5, lane = threadIdx.x & 31;
    size_t row = (size_t)blockIdx.x * 8 + warp;
    float4 v = ((const float4*)(act + row * CC))[lane];
    float s = v.x + v.y + v.z + v.w;
    float q = v.x * v.x + v.y * v.y + v.z * v.z + v.w * v.w;
#pragma unroll
    for (int o = 16; o; o >>= 1) {
        s += __shfl_xor_sync(0xffffffffu, s, o);
        q += __shfl_xor_sync(0xffffffffu, q, o);
    }
    float m = s * (1.0f / CC);
    float var = q * (1.0f / CC) - m * m;
    float rs = rsqrtf(var + 1e-5f);
    float4 sc = ((const float4*)scale)[lane];
    float4 of = ((const float4*)offset)[lane];
    float4 o;
    o.x = (v.x - m) * rs * sc.x + of.x;
    o.y = (v.y - m) * rs * sc.y + of.y;
    o.z = (v.z - m) * rs * sc.z + of.z;
    o.w = (v.w - m) * rs * sc.w + of.w;
    ((float4*)(g_x + row * CC))[lane] = o;
}

// ---------------------------------------------------------------------------
// K2: proj = (x@w_proj)*sigmoid(x@w_gate)*mask, scattered into pair layout:
//     d even -> g_a[d/2][r], d odd -> g_b[d/2][r]
// Tile: 64 rows x 64 d-cols, K chunks of 16. tx (t&15) -> rows, ty -> cols.
// ---------------------------------------------------------------------------
__global__ void k_projgate(const float* __restrict__ wproj,
                           const float* __restrict__ wgate,
                           const float* __restrict__ mask) {
    __shared__ float xs[16][68];
    __shared__ float wp[16][68];
    __shared__ float wg[16][68];
    int t = threadIdx.x;
    int tx = t & 15, ty = t >> 4;
    size_t rbase = (size_t)blockIdx.x * 64;
    int dbase = blockIdx.y * 64;

    float accP[4][4] = {}, accG[4][4] = {};

    int lr = t >> 2, lk = t & 3;           // x-tile load mapping
    int wc = t >> 4, wd4 = (t & 15) * 4;   // weight-tile load mapping

    for (int kc = 0; kc < CC; kc += 16) {
        float4 xv = *(const float4*)(g_x + (rbase + lr) * CC + kc + lk * 4);
        float4 pv = *(const float4*)(wproj + (size_t)(kc + wc) * 256 + dbase + wd4);
        float4 gv = *(const float4*)(wgate + (size_t)(kc + wc) * 256 + dbase + wd4);
        __syncthreads();
        xs[lk * 4 + 0][lr] = xv.x;
        xs[lk * 4 + 1][lr] = xv.y;
        xs[lk * 4 + 2][lr] = xv.z;
        xs[lk * 4 + 3][lr] = xv.w;
        *(float4*)&wp[wc][wd4] = pv;
        *(float4*)&wg[wc][wd4] = gv;
        __syncthreads();
#pragma unroll
        for (int k = 0; k < 16; k++) {
            float4 xr = *(float4*)&xs[k][tx * 4];
            float4 pr = *(float4*)&wp[k][ty * 4];
            float4 gr = *(float4*)&wg[k][ty * 4];
            float xa[4] = {xr.x, xr.y, xr.z, xr.w};
            float pa[4] = {pr.x, pr.y, pr.z, pr.w};
            float ga[4] = {gr.x, gr.y, gr.z, gr.w};
#pragma unroll
            for (int u = 0; u < 4; u++)
#pragma unroll
                for (int v = 0; v < 4; v++) {
                    accP[u][v] += xa[u] * pa[v];
                    accG[u][v] += xa[u] * ga[v];
                }
        }
    }

    float4 mv = *(const float4*)(mask + rbase + tx * 4);
    float mk[4] = {mv.x, mv.y, mv.z, mv.w};
#pragma unroll
    for (int v = 0; v < 4; v++) {
        int d = dbase + ty * 4 + v;
        int c = d >> 1;
        float* dst = (d & 1) ? g_b : g_a;
        float4 o;
        o.x = accP[0][v] * sigm(accG[0][v]) * mk[0];
        o.y = accP[1][v] * sigm(accG[1][v]) * mk[1];
        o.z = accP[2][v] * sigm(accG[2][v]) * mk[2];
        o.w = accP[3][v] * sigm(accG[3][v]) * mk[3];
        *(float4*)(dst + (size_t)c * RR + rbase + tx * 4) = o;
    }
}

// ---------------------------------------------------------------------------
// K3: batched NT GEMM: act2[c] = a[c] (512x512) @ b[c]^T (512x512), K=512.
// 64x64 tile, BK=16, 4x4 microtile. tx -> j (coalesced float4 C writes).
// ---------------------------------------------------------------------------
__global__ void k_pairmm() {
    __shared__ float as[16][68];
    __shared__ float bs[16][68];
    int t = threadIdx.x;
    int tx = t & 15, ty = t >> 4;
    int c = blockIdx.z;
    int ib = blockIdx.y * 64, jb = blockIdx.x * 64;
    const float* A = g_a + (size_t)c * RR;
    const float* B = g_b + (size_t)c * RR;

    float acc[4][4] = {};
    int lr = t >> 2, lk = t & 3;

    for (int kc = 0; kc < NN; kc += 16) {
        float4 av = *(const float4*)(A + (size_t)(ib + lr) * NN + kc + lk * 4);
        float4 bv = *(const float4*)(B + (size_t)(jb + lr) * NN + kc + lk * 4);
        __syncthreads();
        as[lk * 4 + 0][lr] = av.x;
        as[lk * 4 + 1][lr] = av.y;
        as[lk * 4 + 2][lr] = av.z;
        as[lk * 4 + 3][lr] = av.w;
        bs[lk * 4 + 0][lr] = bv.x;
        bs[lk * 4 + 1][lr] = bv.y;
        bs[lk * 4 + 2][lr] = bv.z;
        bs[lk * 4 + 3][lr] = bv.w;
        __syncthreads();
#pragma unroll
        for (int k = 0; k < 16; k++) {
            float4 ar = *(float4*)&as[k][ty * 4];
            float4 br = *(float4*)&bs[k][tx * 4];
            float aa[4] = {ar.x, ar.y, ar.z, ar.w};
            float bb[4] = {br.x, br.y, br.z, br.w};
#pragma unroll
            for (int u = 0; u < 4; u++)
#pragma unroll
                for (int v = 0; v < 4; v++)
                    acc[u][v] += aa[u] * bb[v];
        }
    }

    float* Cp = g_act2 + (size_t)c * RR;
#pragma unroll
    for (int u = 0; u < 4; u++) {
        int i = ib + ty * 4 + u;
        float4 o = make_float4(acc[u][0], acc[u][1], acc[u][2], acc[u][3]);
        *(float4*)(Cp + (size_t)i * NN + jb + tx * 4) = o;
    }
}

// ---------------------------------------------------------------------------
// K4: channel-norm stats (mean/var over c=128) per (i,j).
// ---------------------------------------------------------------------------
__global__ void k_cstats() {
    size_t r = (size_t)blockIdx.x * 256 + threadIdx.x;
    float s = 0.0f, q = 0.0f;
#pragma unroll 8
    for (int c = 0; c < CC; c++) {
        float v = g_act2[(size_t)c * RR + r];
        s += v;
        q += v * v;
    }
    float m = s * (1.0f / CC);
    float var = q * (1.0f / CC) - m * m;
    g_mean[r] = m;
    g_rstd[r] = rsqrtf(var + 1e-5f);
}

// ---------------------------------------------------------------------------
// K5: out[r,e] = (sum_c A2n[c,r]*w_out[c,e] + b_out[e])
//               * sigmoid(sum_c x[r,c]*w_go[c,e] + b_go[e])
// A2n applied on smem load. 64 rows x 64 cols tiles, grid.y=2 covers e=128.
// ---------------------------------------------------------------------------
__global__ void k_final(const float* __restrict__ cs, const float* __restrict__ co,
                        const float* __restrict__ wout, const float* __restrict__ bout,
                        const float* __restrict__ wgo, const float* __restrict__ bgo,
                        float* __restrict__ out) {
    __shared__ float a1s[16][68];
    __shared__ float a2s[16][68];
    __shared__ float w1s[16][68];
    __shared__ float w2s[16][68];
    int t = threadIdx.x;
    int tx = t & 15, ty = t >> 4;
    size_t rb = (size_t)blockIdx.x * 64;
    int eb = blockIdx.y * 64;

    float acc1[4][4] = {}, acc2[4][4] = {};

    int lcc = t >> 4, lr4 = (t & 15) * 4;  // act2 / weight load mapping
    int xr = t >> 2, xk = t & 3;           // x transpose-load mapping

    for (int kc = 0; kc < CC; kc += 16) {
        int c1 = kc + lcc;
        float4 rv = *(const float4*)(g_act2 + (size_t)c1 * RR + rb + lr4);
        float4 mv = *(const float4*)(g_mean + rb + lr4);
        float4 sv = *(const float4*)(g_rstd + rb + lr4);
        float csv = cs[c1], cov = co[c1];
        float4 a1;
        a1.x = (rv.x - mv.x) * sv.x * csv + cov;
        a1.y = (rv.y - mv.y) * sv.y * csv + cov;
        a1.z = (rv.z - mv.z) * sv.z * csv + cov;
        a1.w = (rv.w - mv.w) * sv.w * csv + cov;
        float4 xv = *(const float4*)(g_x + (rb + xr) * CC + kc + xk * 4);
        float4 w1 = *(const float4*)(wout + (size_t)c1 * CC + eb + lr4);
        float4 w2 = *(const float4*)(wgo + (size_t)c1 * CC + eb + lr4);
        __syncthreads();
        *(float4*)&a1s[lcc][lr4] = a1;
        a2s[xk * 4 + 0][xr] = xv.x;
        a2s[xk * 4 + 1][xr] = xv.y;
        a2s[xk * 4 + 2][xr] = xv.z;
        a2s[xk * 4 + 3][xr] = xv.w;
        *(float4*)&w1s[lcc][lr4] = w1;
        *(float4*)&w2s[lcc][lr4] = w2;
        __syncthreads();
#pragma unroll
        for (int k = 0; k < 16; k++) {
            float4 ar1 = *(float4*)&a1s[k][ty * 4];
            float4 ar2 = *(float4*)&a2s[k][ty * 4];
            float4 wr1 = *(float4*)&w1s[k][tx * 4];
            float4 wr2 = *(float4*)&w2s[k][tx * 4];
            float aa1[4] = {ar1.x, ar1.y, ar1.z, ar1.w};
            float aa2[4] = {ar2.x, ar2.y, ar2.z, ar2.w};
            float ww1[4] = {wr1.x, wr1.y, wr1.z, wr1.w};
            float ww2[4] = {wr2.x, wr2.y, wr2.z, wr2.w};
#pragma unroll
            for (int u = 0; u < 4; u++)
#pragma unroll
                for (int v = 0; v < 4; v++) {
                    acc1[u][v] += aa1[u] * ww1[v];
                    acc2[u][v] += aa2[u] * ww2[v];
                }
        }
    }

    int e0 = eb + tx * 4;
    float4 b1 = *(const float4*)(bout + e0);
    float4 b2 = *(const float4*)(bgo + e0);
    float bo[4] = {b1.x, b1.y, b1.z, b1.w};
    float bg[4] = {b2.x, b2.y, b2.z, b2.w};
#pragma unroll
    for (int u = 0; u < 4; u++) {
        size_t r = rb + ty * 4 + u;
        float4 o;
        o.x = (acc1[u][0] + bo[0]) * sigm(acc2[u][0] + bg[0]);
        o.y = (acc1[u][1] + bo[1]) * sigm(acc2[u][1] + bg[1]);
        o.z = (acc1[u][2] + bo[2]) * sigm(acc2[u][2] + bg[2]);
        o.w = (acc1[u][3] + bo[3]) * sigm(acc2[u][3] + bg[3]);
        *(float4*)(out + r * CC + e0) = o;
    }
}

// ---------------------------------------------------------------------------
extern "C" void kernel_launch(void* const* d_in, const int* in_sizes, int n_in,
                              void* d_out, int out_size) {
    const float* act   = (const float*)d_in[0];
    const float* mask  = (const float*)d_in[1];
    const float* ln_s  = (const float*)d_in[2];
    const float* ln_o  = (const float*)d_in[3];
    const float* wproj = (const float*)d_in[4];
    const float* wgate = (const float*)d_in[5];
    const float* cn_s  = (const float*)d_in[6];
    const float* cn_o  = (const float*)d_in[7];
    const float* wout  = (const float*)d_in[8];
    const float* bout  = (const float*)d_in[9];
    const float* wgo   = (const float*)d_in[10];
    const float* bgo   = (const float*)d_in[11];
    float* out = (float*)d_out;

    k_layernorm<<<(int)(RR / 8), 256>>>(act, ln_s, ln_o);
    k_projgate<<<dim3((unsigned)(RR / 64), 4), 256>>>(wproj, wgate, mask);
    k_pairmm<<<dim3(8, 8, 128), 256>>>();
    k_cstats<<<(int)(RR / 256), 256>>>();
    k_final<<<dim3((unsigned)(RR / 64), 2), 256>>>(cn_s, cn_o, wout, bout, wgo, bgo, out);
}

// round 3
// speedup vs baseline: 1.3533x; 1.3533x over previous
#include <cuda_runtime.h>
#include <cuda_bf16.h>
#include <math.h>
#include <cstdint>

// Problem constants (fixed shapes)
#define NN 512
#define CC 128
constexpr size_t RR = (size_t)NN * NN;        // 262144 rows (i,j)
constexpr size_t RC = RR * CC;                // 33.5M elems

// Scratch (device globals; no runtime allocation allowed)
__device__ float g_x[RC];                 // layernormed input, (r, c) row-major
__device__ __nv_bfloat16 g_ah[RC];        // a hi, [c][i][k]
__device__ __nv_bfloat16 g_al[RC];        // a lo
__device__ __nv_bfloat16 g_bh[RC];        // b hi, [c][j][k]
__device__ __nv_bfloat16 g_bl[RC];        // b lo
__device__ float g_act2[RC];              // act2[c][i][j]
__device__ float g_mean[RR];
__device__ float g_rstd[RR];

__device__ __forceinline__ float sigm(float z) { return 1.0f / (1.0f + __expf(-z)); }

__device__ __forceinline__ uint32_t smem_u32(const void* p) {
    uint32_t a;
    asm("{ .reg .u64 t; cvta.to.shared.u64 t, %1; cvt.u32.u64 %0, t; }" : "=r"(a) : "l"(p));
    return a;
}
__device__ __forceinline__ void cp_async16(uint32_t dst, const void* src) {
    asm volatile("cp.async.cg.shared.global [%0], [%1], 16;" :: "r"(dst), "l"(src));
}
#define CP_COMMIT() asm volatile("cp.async.commit_group;" ::: "memory")
#define CP_WAIT1()  asm volatile("cp.async.wait_group 1;" ::: "memory")

__device__ __forceinline__ void ldsm4(uint32_t addr, uint32_t* r) {
    asm volatile("ldmatrix.sync.aligned.m8n8.x4.shared.b16 {%0,%1,%2,%3}, [%4];"
                 : "=r"(r[0]), "=r"(r[1]), "=r"(r[2]), "=r"(r[3]) : "r"(addr));
}
__device__ __forceinline__ void ldsm2(uint32_t addr, uint32_t* r) {
    asm volatile("ldmatrix.sync.aligned.m8n8.x2.shared.b16 {%0,%1}, [%2];"
                 : "=r"(r[0]), "=r"(r[1]) : "r"(addr));
}
__device__ __forceinline__ void mma16816(float* d, const uint32_t* a, const uint32_t* b) {
    asm volatile("mma.sync.aligned.m16n8k16.row.col.f32.bf16.bf16.f32 "
                 "{%0,%1,%2,%3}, {%4,%5,%6,%7}, {%8,%9}, {%0,%1,%2,%3};"
                 : "+f"(d[0]), "+f"(d[1]), "+f"(d[2]), "+f"(d[3])
                 : "r"(a[0]), "r"(a[1]), "r"(a[2]), "r"(a[3]), "r"(b[0]), "r"(b[1]));
}

// ---------------------------------------------------------------------------
// K1: LayerNorm over last dim (C=128). One warp per row; float4 per lane.
// ---------------------------------------------------------------------------
__global__ void k_layernorm(const float* __restrict__ act,
                            const float* __restrict__ scale,
                            const float* __restrict__ offset) {
    int warp = threadIdx.x >> 5, lane = threadIdx.x & 31;
    size_t row = (size_t)blockIdx.x * 8 + warp;
    float4 v = ((const float4*)(act + row * CC))[lane];
    float s = v.x + v.y + v.z + v.w;
    float q = v.x * v.x + v.y * v.y + v.z * v.z + v.w * v.w;
#pragma unroll
    for (int o = 16; o; o >>= 1) {
        s += __shfl_xor_sync(0xffffffffu, s, o);
        q += __shfl_xor_sync(0xffffffffu, q, o);
    }
    float m = s * (1.0f / CC);
    float var = q * (1.0f / CC) - m * m;
    float rs = rsqrtf(var + 1e-5f);
    float4 sc = ((const float4*)scale)[lane];
    float4 of = ((const float4*)offset)[lane];
    float4 o;
    o.x = (v.x - m) * rs * sc.x + of.x;
    o.y = (v.y - m) * rs * sc.y + of.y;
    o.z = (v.z - m) * rs * sc.z + of.z;
    o.w = (v.w - m) * rs * sc.w + of.w;
    ((float4*)(g_x + row * CC))[lane] = o;
}

// ---------------------------------------------------------------------------
// K2: proj = (x@w_proj)*sigmoid(x@w_gate)*mask, scattered into pair layout
//     as bf16 hi/lo splits: d even -> a[d/2], d odd -> b[d/2].
// ---------------------------------------------------------------------------
__global__ void k_projgate(const float* __restrict__ wproj,
                           const float* __restrict__ wgate,
                           const float* __restrict__ mask) {
    __shared__ float xs[16][68];
    __shared__ float wp[16][68];
    __shared__ float wg[16][68];
    int t = threadIdx.x;
    int tx = t & 15, ty = t >> 4;
    size_t rbase = (size_t)blockIdx.x * 64;
    int dbase = blockIdx.y * 64;

    float accP[4][4] = {}, accG[4][4] = {};

    int lr = t >> 2, lk = t & 3;
    int wc = t >> 4, wd4 = (t & 15) * 4;

    for (int kc = 0; kc < CC; kc += 16) {
        float4 xv = *(const float4*)(g_x + (rbase + lr) * CC + kc + lk * 4);
        float4 pv = *(const float4*)(wproj + (size_t)(kc + wc) * 256 + dbase + wd4);
        float4 gv = *(const float4*)(wgate + (size_t)(kc + wc) * 256 + dbase + wd4);
        __syncthreads();
        xs[lk * 4 + 0][lr] = xv.x;
        xs[lk * 4 + 1][lr] = xv.y;
        xs[lk * 4 + 2][lr] = xv.z;
        xs[lk * 4 + 3][lr] = xv.w;
        *(float4*)&wp[wc][wd4] = pv;
        *(float4*)&wg[wc][wd4] = gv;
        __syncthreads();
#pragma unroll
        for (int k = 0; k < 16; k++) {
            float4 xr = *(float4*)&xs[k][tx * 4];
            float4 pr = *(float4*)&wp[k][ty * 4];
            float4 gr = *(float4*)&wg[k][ty * 4];
            float xa[4] = {xr.x, xr.y, xr.z, xr.w};
            float pa[4] = {pr.x, pr.y, pr.z, pr.w};
            float ga[4] = {gr.x, gr.y, gr.z, gr.w};
#pragma unroll
            for (int u = 0; u < 4; u++)
#pragma unroll
                for (int v = 0; v < 4; v++) {
                    accP[u][v] += xa[u] * pa[v];
                    accG[u][v] += xa[u] * ga[v];
                }
        }
    }

    float4 mv = *(const float4*)(mask + rbase + tx * 4);
    float mk[4] = {mv.x, mv.y, mv.z, mv.w};
#pragma unroll
    for (int v = 0; v < 4; v++) {
        int d = dbase + ty * 4 + v;
        int c = d >> 1;
        __nv_bfloat16* dh = (d & 1) ? g_bh : g_ah;
        __nv_bfloat16* dl = (d & 1) ? g_bl : g_al;
        size_t idx = (size_t)c * RR + rbase + tx * 4;
        unsigned short hs[4], ls[4];
#pragma unroll
        for (int u = 0; u < 4; u++) {
            float val = accP[u][v] * sigm(accG[u][v]) * mk[u];
            __nv_bfloat16 h = __float2bfloat16(val);
            float rem = val - __bfloat162float(h);
            __nv_bfloat16 l = __float2bfloat16(rem);
            hs[u] = __bfloat16_as_ushort(h);
            ls[u] = __bfloat16_as_ushort(l);
        }
        uint2 hv = make_uint2((uint32_t)hs[0] | ((uint32_t)hs[1] << 16),
                              (uint32_t)hs[2] | ((uint32_t)hs[3] << 16));
        uint2 lv = make_uint2((uint32_t)ls[0] | ((uint32_t)ls[1] << 16),
                              (uint32_t)ls[2] | ((uint32_t)ls[3] << 16));
        *(uint2*)(dh + idx) = hv;
        *(uint2*)(dl + idx) = lv;
    }
}

// ---------------------------------------------------------------------------
// K3 (mma.sync bf16): act2[c] = a[c] @ b[c]^T, 128x128 tile/CTA, K=512.
// 3-term split: D = Ah*Bh + Ah*Bl + Al*Bh  (fp32 accumulators).
// BK=32, double-buffered cp.async, padded 80B smem rows (conflict-free).
// 8 warps: 2x4 grid of 64x32 warp tiles.
// ---------------------------------------------------------------------------
#define PM_TILE_B   10240              // 128 rows * 80 B
#define PM_STAGE_B  (4 * PM_TILE_B)    // Ah, Al, Bh, Bl
#define PM_SMEM_BYTES (2 * PM_STAGE_B) // 81920

__device__ __forceinline__ void pm_load_stage(uint32_t stageBase, int kc,
                                              size_t cOff, int ib, int jb, int t) {
    const __nv_bfloat16* srcs[4] = {g_ah, g_al, g_bh, g_bl};
#pragma unroll
    for (int tile = 0; tile < 4; tile++) {
        const int rb = (tile < 2) ? ib : jb;
        const __nv_bfloat16* src = srcs[tile] + cOff;
        const uint32_t tb = stageBase + tile * PM_TILE_B;
#pragma unroll
        for (int it = 0; it < 2; it++) {
            int idx = it * 256 + t;          // 0..511
            int r = idx >> 2, ch = idx & 3;  // row, 16B chunk
            cp_async16(tb + r * 80 + ch * 16,
                       src + (size_t)(rb + r) * NN + kc + ch * 8);
        }
    }
}

__global__ void __launch_bounds__(256, 1) k_pairmm_mma() {
    extern __shared__ char smem[];
    const uint32_t sbase = smem_u32(smem);
    const int t = threadIdx.x, lane = t & 31, wid = t >> 5;
    const int c = blockIdx.z;
    const int ib = blockIdx.y * 128, jb = blockIdx.x * 128;
    const size_t cOff = (size_t)c * RR;
    const int m0 = (wid >> 2) * 64, n0 = (wid & 3) * 32;

    float acc[4][4][4] = {};

    pm_load_stage(sbase, 0, cOff, ib, jb, t);
    CP_COMMIT();
    pm_load_stage(sbase + PM_STAGE_B, 32, cOff, ib, jb, t);
    CP_COMMIT();

    for (int kch = 0; kch < 16; kch++) {
        CP_WAIT1();
        __syncthreads();
        const uint32_t sb = sbase + (kch & 1) * PM_STAGE_B;
        const uint32_t aH = sb + (m0 + (lane & 15)) * 80 + (lane >> 4) * 16;
        const uint32_t aL = aH + PM_TILE_B;
        const uint32_t bH = sb + 2 * PM_TILE_B + (n0 + (lane & 7)) * 80 + ((lane >> 3) & 1) * 16;
        const uint32_t bL = bH + PM_TILE_B;
#pragma unroll
        for (int kk = 0; kk < 2; kk++) {
            const uint32_t ko = kk * 32;   // 16 bf16 = 32 B
            uint32_t ah[4][4], al[4][4], bh[4][2], bl[4][2];
#pragma unroll
            for (int mi = 0; mi < 4; mi++) {
                ldsm4(aH + mi * 1280 + ko, ah[mi]);
                ldsm4(aL + mi * 1280 + ko, al[mi]);
            }
#pragma unroll
            for (int ni = 0; ni < 4; ni++) {
                ldsm2(bH + ni * 640 + ko, bh[ni]);
                ldsm2(bL + ni * 640 + ko, bl[ni]);
            }
#pragma unroll
            for (int mi = 0; mi < 4; mi++)
#pragma unroll
                for (int ni = 0; ni < 4; ni++) {
                    mma16816(acc[mi][ni], ah[mi], bh[ni]);
                    mma16816(acc[mi][ni], ah[mi], bl[ni]);
                    mma16816(acc[mi][ni], al[mi], bh[ni]);
                }
        }
        __syncthreads();
        if (kch + 2 < 16)
            pm_load_stage(sbase + (kch & 1) * PM_STAGE_B, (kch + 2) * 32, cOff, ib, jb, t);
        CP_COMMIT();
    }

    // Epilogue: fragment -> gmem (32B-sector coalesced float2 stores)
    float* Cp = g_act2 + cOff;
    const int mr = lane >> 2, nc = (lane & 3) * 2;
#pragma unroll
    for (int mi = 0; mi < 4; mi++) {
#pragma unroll
        for (int ni = 0; ni < 4; ni++) {
            size_t row0 = (size_t)(ib + m0 + mi * 16 + mr) * NN + jb + n0 + ni * 8 + nc;
            *(float2*)(Cp + row0)          = make_float2(acc[mi][ni][0], acc[mi][ni][1]);
            *(float2*)(Cp + row0 + 8 * NN) = make_float2(acc[mi][ni][2], acc[mi][ni][3]);
        }
    }
}

// ---------------------------------------------------------------------------
// K4: channel-norm stats (mean/var over c=128) per (i,j).
// ---------------------------------------------------------------------------
__global__ void k_cstats() {
    size_t r = (size_t)blockIdx.x * 256 + threadIdx.x;
    float s = 0.0f, q = 0.0f;
#pragma unroll 8
    for (int c = 0; c < CC; c++) {
        float v = g_act2[(size_t)c * RR + r];
        s += v;
        q += v * v;
    }
    float m = s * (1.0f / CC);
    float var = q * (1.0f / CC) - m * m;
    g_mean[r] = m;
    g_rstd[r] = rsqrtf(var + 1e-5f);
}

// ---------------------------------------------------------------------------
// K5: out[r,e] = (sum_c A2n[c,r]*w_out[c,e] + b_out[e])
//               * sigmoid(sum_c x[r,c]*w_go[c,e] + b_go[e])
// ---------------------------------------------------------------------------
__global__ void k_final(const float* __restrict__ cs, const float* __restrict__ co,
                        const float* __restrict__ wout, const float* __restrict__ bout,
                        const float* __restrict__ wgo, const float* __restrict__ bgo,
                        float* __restrict__ out) {
    __shared__ float a1s[16][68];
    __shared__ float a2s[16][68];
    __shared__ float w1s[16][68];
    __shared__ float w2s[16][68];
    int t = threadIdx.x;
    int tx = t & 15, ty = t >> 4;
    size_t rb = (size_t)blockIdx.x * 64;
    int eb = blockIdx.y * 64;

    float acc1[4][4] = {}, acc2[4][4] = {};

    int lcc = t >> 4, lr4 = (t & 15) * 4;
    int xr = t >> 2, xk = t & 3;

    for (int kc = 0; kc < CC; kc += 16) {
        int c1 = kc + lcc;
        float4 rv = *(const float4*)(g_act2 + (size_t)c1 * RR + rb + lr4);
        float4 mv = *(const float4*)(g_mean + rb + lr4);
        float4 sv = *(const float4*)(g_rstd + rb + lr4);
        float csv = cs[c1], cov = co[c1];
        float4 a1;
        a1.x = (rv.x - mv.x) * sv.x * csv + cov;
        a1.y = (rv.y - mv.y) * sv.y * csv + cov;
        a1.z = (rv.z - mv.z) * sv.z * csv + cov;
        a1.w = (rv.w - mv.w) * sv.w * csv + cov;
        float4 xv = *(const float4*)(g_x + (rb + xr) * CC + kc + xk * 4);
        float4 w1 = *(const float4*)(wout + (size_t)c1 * CC + eb + lr4);
        float4 w2 = *(const float4*)(wgo + (size_t)c1 * CC + eb + lr4);
        __syncthreads();
        *(float4*)&a1s[lcc][lr4] = a1;
        a2s[xk * 4 + 0][xr] = xv.x;
        a2s[xk * 4 + 1][xr] = xv.y;
        a2s[xk * 4 + 2][xr] = xv.z;
        a2s[xk * 4 + 3][xr] = xv.w;
        *(float4*)&w1s[lcc][lr4] = w1;
        *(float4*)&w2s[lcc][lr4] = w2;
        __syncthreads();
#pragma unroll
        for (int k = 0; k < 16; k++) {
            float4 ar1 = *(float4*)&a1s[k][ty * 4];
            float4 ar2 = *(float4*)&a2s[k][ty * 4];
            float4 wr1 = *(float4*)&w1s[k][tx * 4];
            float4 wr2 = *(float4*)&w2s[k][tx * 4];
            float aa1[4] = {ar1.x, ar1.y, ar1.z, ar1.w};
            float aa2[4] = {ar2.x, ar2.y, ar2.z, ar2.w};
            float ww1[4] = {wr1.x, wr1.y, wr1.z, wr1.w};
            float ww2[4] = {wr2.x, wr2.y, wr2.z, wr2.w};
#pragma unroll
            for (int u = 0; u < 4; u++)
#pragma unroll
                for (int v = 0; v < 4; v++) {
                    acc1[u][v] += aa1[u] * ww1[v];
                    acc2[u][v] += aa2[u] * ww2[v];
                }
        }
    }

    int e0 = eb + tx * 4;
    float4 b1 = *(const float4*)(bout + e0);
    float4 b2 = *(const float4*)(bgo + e0);
    float bo[4] = {b1.x, b1.y, b1.z, b1.w};
    float bg[4] = {b2.x, b2.y, b2.z, b2.w};
#pragma unroll
    for (int u = 0; u < 4; u++) {
        size_t r = rb + ty * 4 + u;
        float4 o;
        o.x = (acc1[u][0] + bo[0]) * sigm(acc2[u][0] + bg[0]);
        o.y = (acc1[u][1] + bo[1]) * sigm(acc2[u][1] + bg[1]);
        o.z = (acc1[u][2] + bo[2]) * sigm(acc2[u][2] + bg[2]);
        o.w = (acc1[u][3] + bo[3]) * sigm(acc2[u][3] + bg[3]);
        *(float4*)(out + r * CC + e0) = o;
    }
}

// ---------------------------------------------------------------------------
extern "C" void kernel_launch(void* const* d_in, const int* in_sizes, int n_in,
                              void* d_out, int out_size) {
    const float* act   = (const float*)d_in[0];
    const float* mask  = (const float*)d_in[1];
    const float* ln_s  = (const float*)d_in[2];
    const float* ln_o  = (const float*)d_in[3];
    const float* wproj = (const float*)d_in[4];
    const float* wgate = (const float*)d_in[5];
    const float* cn_s  = (const float*)d_in[6];
    const float* cn_o  = (const float*)d_in[7];
    const float* wout  = (const float*)d_in[8];
    const float* bout  = (const float*)d_in[9];
    const float* wgo   = (const float*)d_in[10];
    const float* bgo   = (const float*)d_in[11];
    float* out = (float*)d_out;

    cudaFuncSetAttribute(k_pairmm_mma, cudaFuncAttributeMaxDynamicSharedMemorySize,
                         PM_SMEM_BYTES);

    k_layernorm<<<(int)(RR / 8), 256>>>(act, ln_s, ln_o);
    k_projgate<<<dim3((unsigned)(RR / 64), 4), 256>>>(wproj, wgate, mask);
    k_pairmm_mma<<<dim3(4, 4, 128), 256, PM_SMEM_BYTES>>>();
    k_cstats<<<(int)(RR / 256), 256>>>();
    k_final<<<dim3((unsigned)(RR / 64), 2), 256>>>(cn_s, cn_o, wout, bout, wgo, bgo, out);
}

// round 4
// speedup vs baseline: 1.5248x; 1.1267x over previous
#include <cuda_runtime.h>
#include <cuda_bf16.h>
#include <math.h>
#include <cstdint>

// Problem constants (fixed shapes)
#define NN 512
#define CC 128
constexpr size_t RR = (size_t)NN * NN;        // 262144 rows (i,j)
constexpr size_t RC = RR * CC;                // 33.5M elems

// Scratch (device globals; no runtime allocation allowed)
__device__ __nv_bfloat16 g_xh[RC];        // layernormed x hi, [r][c]
__device__ __nv_bfloat16 g_xl[RC];        // x lo
__device__ __nv_bfloat16 g_ah[RC];        // a hi, [c][i][k]
__device__ __nv_bfloat16 g_al[RC];
__device__ __nv_bfloat16 g_bh[RC];        // b hi, [c][j][k]
__device__ __nv_bfloat16 g_bl[RC];
__device__ float g_act2[RC];              // act2[c][i][j] fp32
__device__ float g_mean[RR];
__device__ float g_rstd[RR];

// Prepped weights (transposed to [n][k], bf16 hi/lo)
__device__ __nv_bfloat16 g_wph[256 * CC], g_wpl[256 * CC];   // w_proj^T
__device__ __nv_bfloat16 g_wgh[256 * CC], g_wgl[256 * CC];   // w_gate^T
__device__ __nv_bfloat16 g_w1h[CC * CC], g_w1l[CC * CC];     // (cs ⊙ w_out)^T
__device__ __nv_bfloat16 g_w2h[CC * CC], g_w2l[CC * CC];     // w_gate_out^T
__device__ float g_S1[CC], g_S2[CC];

__device__ __forceinline__ float sigm(float z) { return 1.0f / (1.0f + __expf(-z)); }

__device__ __forceinline__ void split_bf16(float v, unsigned short& h, unsigned short& l) {
    __nv_bfloat16 hb = __float2bfloat16(v);
    float rem = v - __bfloat162float(hb);
    __nv_bfloat16 lb = __float2bfloat16(rem);
    h = __bfloat16_as_ushort(hb);
    l = __bfloat16_as_ushort(lb);
}

__device__ __forceinline__ uint32_t smem_u32(const void* p) {
    uint32_t a;
    asm("{ .reg .u64 t; cvta.to.shared.u64 t, %1; cvt.u32.u64 %0, t; }" : "=r"(a) : "l"(p));
    return a;
}
__device__ __forceinline__ void cp_async16(uint32_t dst, const void* src) {
    asm volatile("cp.async.cg.shared.global [%0], [%1], 16;" :: "r"(dst), "l"(src));
}
#define CP_COMMIT() asm volatile("cp.async.commit_group;" ::: "memory")
#define CP_WAIT1()  asm volatile("cp.async.wait_group 1;" ::: "memory")
#define CP_WAIT0()  asm volatile("cp.async.wait_group 0;" ::: "memory")

__device__ __forceinline__ void ldsm4(uint32_t addr, uint32_t* r) {
    asm volatile("ldmatrix.sync.aligned.m8n8.x4.shared.b16 {%0,%1,%2,%3}, [%4];"
                 : "=r"(r[0]), "=r"(r[1]), "=r"(r[2]), "=r"(r[3]) : "r"(addr));
}
__device__ __forceinline__ void ldsm2(uint32_t addr, uint32_t* r) {
    asm volatile("ldmatrix.sync.aligned.m8n8.x2.shared.b16 {%0,%1}, [%2];"
                 : "=r"(r[0]), "=r"(r[1]) : "r"(addr));
}
__device__ __forceinline__ void mma16816(float* d, const uint32_t* a, const uint32_t* b) {
    asm volatile("mma.sync.aligned.m16n8k16.row.col.f32.bf16.bf16.f32 "
                 "{%0,%1,%2,%3}, {%4,%5,%6,%7}, {%8,%9}, {%0,%1,%2,%3};"
                 : "+f"(d[0]), "+f"(d[1]), "+f"(d[2]), "+f"(d[3])
                 : "r"(a[0]), "r"(a[1]), "r"(a[2]), "r"(a[3]), "r"(b[0]), "r"(b[1]));
}

// ---------------------------------------------------------------------------
// K1: LayerNorm over last dim (C=128); emits bf16 hi/lo split of x.
// ---------------------------------------------------------------------------
__global__ void k_layernorm(const float* __restrict__ act,
                            const float* __restrict__ scale,
                            const float* __restrict__ offset) {
    int warp = threadIdx.x >> 5, lane = threadIdx.x & 31;
    size_t row = (size_t)blockIdx.x * 8 + warp;
    float4 v = ((const float4*)(act + row * CC))[lane];
    float s = v.x + v.y + v.z + v.w;
    float q = v.x * v.x + v.y * v.y + v.z * v.z + v.w * v.w;
#pragma unroll
    for (int o = 16; o; o >>= 1) {
        s += __shfl_xor_sync(0xffffffffu, s, o);
        q += __shfl_xor_sync(0xffffffffu, q, o);
    }
    float m = s * (1.0f / CC);
    float var = q * (1.0f / CC) - m * m;
    float rs = rsqrtf(var + 1e-5f);
    float4 sc = ((const float4*)scale)[lane];
    float4 of = ((const float4*)offset)[lane];
    float o[4];
    o[0] = (v.x - m) * rs * sc.x + of.x;
    o[1] = (v.y - m) * rs * sc.y + of.y;
    o[2] = (v.z - m) * rs * sc.z + of.z;
    o[3] = (v.w - m) * rs * sc.w + of.w;
    unsigned short hs[4], ls[4];
#pragma unroll
    for (int u = 0; u < 4; u++) split_bf16(o[u], hs[u], ls[u]);
    uint2 hv = make_uint2((uint32_t)hs[0] | ((uint32_t)hs[1] << 16),
                          (uint32_t)hs[2] | ((uint32_t)hs[3] << 16));
    uint2 lv = make_uint2((uint32_t)ls[0] | ((uint32_t)ls[1] << 16),
                          (uint32_t)ls[2] | ((uint32_t)ls[3] << 16));
    *(uint2*)(g_xh + row * CC + lane * 4) = hv;
    *(uint2*)(g_xl + row * CC + lane * 4) = lv;
}

// ---------------------------------------------------------------------------
// Weight prep kernels
// ---------------------------------------------------------------------------
__global__ void k_prep_pg(const float* __restrict__ wproj,
                          const float* __restrict__ wgate) {
    int idx = blockIdx.x * 256 + threadIdx.x;   // 0..32767
    int d = idx >> 7, c = idx & 127;
    unsigned short h, l;
    split_bf16(wproj[(size_t)c * 256 + d], h, l);
    g_wph[idx] = __ushort_as_bfloat16(h); g_wpl[idx] = __ushort_as_bfloat16(l);
    split_bf16(wgate[(size_t)c * 256 + d], h, l);
    g_wgh[idx] = __ushort_as_bfloat16(h); g_wgl[idx] = __ushort_as_bfloat16(l);
}
__global__ void k_prep_out(const float* __restrict__ wout, const float* __restrict__ wgo,
                           const float* __restrict__ cs) {
    int idx = blockIdx.x * 256 + threadIdx.x;   // 0..16383
    int e = idx >> 7, c = idx & 127;
    unsigned short h, l;
    split_bf16(cs[c] * wout[(size_t)c * CC + e], h, l);
    g_w1h[idx] = __ushort_as_bfloat16(h); g_w1l[idx] = __ushort_as_bfloat16(l);
    split_bf16(wgo[(size_t)c * CC + e], h, l);
    g_w2h[idx] = __ushort_as_bfloat16(h); g_w2l[idx] = __ushort_as_bfloat16(l);
}
__global__ void k_prep_s(const float* __restrict__ wout,
                         const float* __restrict__ cs, const float* __restrict__ co) {
    int e = threadIdx.x;
    float s1 = 0.0f, s2 = 0.0f;
    for (int c = 0; c < CC; c++) {
        float w = wout[(size_t)c * CC + e];
        s1 += cs[c] * w;
        s2 += co[c] * w;
    }
    g_S1[e] = s1; g_S2[e] = s2;
}

// ---------------------------------------------------------------------------
// K2 (mma): proj & gate GEMMs fused. Tile: 128 rows x 64 d, K=128 (BK=32 x4),
// double-buffered cp.async. Epilogue: proj*sigm(gate)*mask -> bf16 hi/lo pair
// scatter via smem transpose.
// ---------------------------------------------------------------------------
#define PG_STAGE_B 40960   // xh,xl: 128*80 each; 4 w arrays: 64*80 each
#define PG_SMEM_BYTES (2 * PG_STAGE_B)

__device__ __forceinline__ void pg_load_stage(uint32_t sb, int kc, size_t rb, int db, int t) {
    {
        const __nv_bfloat16* xs[2] = {g_xh, g_xl};
#pragma unroll
        for (int arr = 0; arr < 2; arr++) {
            uint32_t tb = sb + arr * 10240;
#pragma unroll
            for (int it = 0; it < 2; it++) {
                int idx = it * 256 + t;
                int r = idx >> 2, ch = idx & 3;
                cp_async16(tb + r * 80 + ch * 16, xs[arr] + (rb + r) * CC + kc + ch * 8);
            }
        }
    }
    {
        const __nv_bfloat16* ws[4] = {g_wph, g_wpl, g_wgh, g_wgl};
#pragma unroll
        for (int arr = 0; arr < 4; arr++) {
            uint32_t tb = sb + 20480 + arr * 5120;
            int d = t >> 2, ch = t & 3;
            cp_async16(tb + d * 80 + ch * 16, ws[arr] + (size_t)(db + d) * CC + kc + ch * 8);
        }
    }
}

__global__ void __launch_bounds__(256, 1) k_projgate_mma(const float* __restrict__ mask) {
    extern __shared__ char smem[];
    const uint32_t sbase = smem_u32(smem);
    const int t = threadIdx.x, lane = t & 31, wid = t >> 5;
    const int db = blockIdx.x * 64;
    const size_t rb = (size_t)blockIdx.y * 128;
    const int m0 = (wid >> 2) * 64, n0 = (wid & 3) * 16;

    float accP[4][2][4] = {}, accG[4][2][4] = {};

    pg_load_stage(sbase, 0, rb, db, t);  CP_COMMIT();
    pg_load_stage(sbase + PG_STAGE_B, 32, rb, db, t);  CP_COMMIT();

    for (int kch = 0; kch < 4; kch++) {
        CP_WAIT1();
        __syncthreads();
        const uint32_t sb = sbase + (kch & 1) * PG_STAGE_B;
        const uint32_t aH = sb + (m0 + (lane & 15)) * 80 + (lane >> 4) * 16;
        const uint32_t aL = aH + 10240;
        const uint32_t wb = sb + 20480 + (n0 + (lane & 7)) * 80 + ((lane >> 3) & 1) * 16;
#pragma unroll
        for (int kk = 0; kk < 2; kk++) {
            const uint32_t ko = kk * 32;
            uint32_t ah[4][4], al[4][4];
            uint32_t bph[2][2], bpl[2][2], bgh[2][2], bgl[2][2];
#pragma unroll
            for (int mi = 0; mi < 4; mi++) {
                ldsm4(aH + mi * 1280 + ko, ah[mi]);
                ldsm4(aL + mi * 1280 + ko, al[mi]);
            }
#pragma unroll
            for (int ni = 0; ni < 2; ni++) {
                ldsm2(wb + ni * 640 + ko,          bph[ni]);
                ldsm2(wb + ni * 640 + ko + 5120,   bpl[ni]);
                ldsm2(wb + ni * 640 + ko + 10240,  bgh[ni]);
                ldsm2(wb + ni * 640 + ko + 15360,  bgl[ni]);
            }
#pragma unroll
            for (int mi = 0; mi < 4; mi++)
#pragma unroll
                for (int ni = 0; ni < 2; ni++) {
                    mma16816(accP[mi][ni], ah[mi], bph[ni]);
                    mma16816(accP[mi][ni], ah[mi], bpl[ni]);
                    mma16816(accP[mi][ni], al[mi], bph[ni]);
                    mma16816(accG[mi][ni], ah[mi], bgh[ni]);
                    mma16816(accG[mi][ni], ah[mi], bgl[ni]);
                    mma16816(accG[mi][ni], al[mi], bgh[ni]);
                }
        }
        __syncthreads();
        if (kch + 2 < 4)
            pg_load_stage(sbase + (kch & 1) * PG_STAGE_B, (kch + 2) * 32, rb, db, t);
        CP_COMMIT();
    }

    // Epilogue: stash proj/gate to smem [d][130 r], then coalesced pair writes
    float* bufP = (float*)smem;
    float* bufG = bufP + 64 * 130;
    const int mr = lane >> 2, ncl = (lane & 3) * 2;
#pragma unroll
    for (int mi = 0; mi < 4; mi++)
#pragma unroll
        for (int ni = 0; ni < 2; ni++) {
            int rl = m0 + mi * 16 + mr;
            int dl = n0 + ni * 8 + ncl;
            bufP[dl * 130 + rl]           = accP[mi][ni][0];
            bufP[(dl + 1) * 130 + rl]     = accP[mi][ni][1];
            bufP[dl * 130 + rl + 8]       = accP[mi][ni][2];
            bufP[(dl + 1) * 130 + rl + 8] = accP[mi][ni][3];
            bufG[dl * 130 + rl]           = accG[mi][ni][0];
            bufG[(dl + 1) * 130 + rl]     = accG[mi][ni][1];
            bufG[dl * 130 + rl + 8]       = accG[mi][ni][2];
            bufG[(dl + 1) * 130 + rl + 8] = accG[mi][ni][3];
        }
    __syncthreads();

    int dl = t >> 2, rg = t & 3;
    int dg = db + dl;
    int c = dg >> 1;
    __nv_bfloat16* dsth = (dg & 1) ? g_bh : g_ah;
    __nv_bfloat16* dstl = (dg & 1) ? g_bl : g_al;
    size_t base = (size_t)c * RR + rb + rg * 32;
#pragma unroll
    for (int i4 = 0; i4 < 4; i4++) {
        unsigned short hs[8], ls[8];
#pragma unroll
        for (int j = 0; j < 8; j++) {
            int r = rg * 32 + i4 * 8 + j;
            float val = bufP[dl * 130 + r] * sigm(bufG[dl * 130 + r]) * mask[rb + r];
            split_bf16(val, hs[j], ls[j]);
        }
        uint4 hv = make_uint4((uint32_t)hs[0] | ((uint32_t)hs[1] << 16),
                              (uint32_t)hs[2] | ((uint32_t)hs[3] << 16),
                              (uint32_t)hs[4] | ((uint32_t)hs[5] << 16),
                              (uint32_t)hs[6] | ((uint32_t)hs[7] << 16));
        uint4 lv = make_uint4((uint32_t)ls[0] | ((uint32_t)ls[1] << 16),
                              (uint32_t)ls[2] | ((uint32_t)ls[3] << 16),
                              (uint32_t)ls[4] | ((uint32_t)ls[5] << 16),
                              (uint32_t)ls[6] | ((uint32_t)ls[7] << 16));
        *(uint4*)(dsth + base + i4 * 8) = hv;
        *(uint4*)(dstl + base + i4 * 8) = lv;
    }
}

// ---------------------------------------------------------------------------
// K3 (mma): act2[c] = a[c] @ b[c]^T, 128x128 tile/CTA, K=512 (unchanged R3).
// ---------------------------------------------------------------------------
#define PM_TILE_B   10240
#define PM_STAGE_B  (4 * PM_TILE_B)
#define PM_SMEM_BYTES (2 * PM_STAGE_B)

__device__ __forceinline__ void pm_load_stage(uint32_t stageBase, int kc,
                                              size_t cOff, int ib, int jb, int t) {
    const __nv_bfloat16* srcs[4] = {g_ah, g_al, g_bh, g_bl};
#pragma unroll
    for (int tile = 0; tile < 4; tile++) {
        const int rb = (tile < 2) ? ib : jb;
        const __nv_bfloat16* src = srcs[tile] + cOff;
        const uint32_t tb = stageBase + tile * PM_TILE_B;
#pragma unroll
        for (int it = 0; it < 2; it++) {
            int idx = it * 256 + t;
            int r = idx >> 2, ch = idx & 3;
            cp_async16(tb + r * 80 + ch * 16,
                       src + (size_t)(rb + r) * NN + kc + ch * 8);
        }
    }
}

__global__ void __launch_bounds__(256, 1) k_pairmm_mma() {
    extern __shared__ char smem[];
    const uint32_t sbase = smem_u32(smem);
    const int t = threadIdx.x, lane = t & 31, wid = t >> 5;
    const int c = blockIdx.z;
    const int ib = blockIdx.y * 128, jb = blockIdx.x * 128;
    const size_t cOff = (size_t)c * RR;
    const int m0 = (wid >> 2) * 64, n0 = (wid & 3) * 32;

    float acc[4][4][4] = {};

    pm_load_stage(sbase, 0, cOff, ib, jb, t);
    CP_COMMIT();
    pm_load_stage(sbase + PM_STAGE_B, 32, cOff, ib, jb, t);
    CP_COMMIT();

    for (int kch = 0; kch < 16; kch++) {
        CP_WAIT1();
        __syncthreads();
        const uint32_t sb = sbase + (kch & 1) * PM_STAGE_B;
        const uint32_t aH = sb + (m0 + (lane & 15)) * 80 + (lane >> 4) * 16;
        const uint32_t aL = aH + PM_TILE_B;
        const uint32_t bH = sb + 2 * PM_TILE_B + (n0 + (lane & 7)) * 80 + ((lane >> 3) & 1) * 16;
        const uint32_t bL = bH + PM_TILE_B;
#pragma unroll
        for (int kk = 0; kk < 2; kk++) {
            const uint32_t ko = kk * 32;
            uint32_t ah[4][4], al[4][4], bh[4][2], bl[4][2];
#pragma unroll
            for (int mi = 0; mi < 4; mi++) {
                ldsm4(aH + mi * 1280 + ko, ah[mi]);
                ldsm4(aL + mi * 1280 + ko, al[mi]);
            }
#pragma unroll
            for (int ni = 0; ni < 4; ni++) {
                ldsm2(bH + ni * 640 + ko, bh[ni]);
                ldsm2(bL + ni * 640 + ko, bl[ni]);
            }
#pragma unroll
            for (int mi = 0; mi < 4; mi++)
#pragma unroll
                for (int ni = 0; ni < 4; ni++) {
                    mma16816(acc[mi][ni], ah[mi], bh[ni]);
                    mma16816(acc[mi][ni], ah[mi], bl[ni]);
                    mma16816(acc[mi][ni], al[mi], bh[ni]);
                }
        }
        __syncthreads();
        if (kch + 2 < 16)
            pm_load_stage(sbase + (kch & 1) * PM_STAGE_B, (kch + 2) * 32, cOff, ib, jb, t);
        CP_COMMIT();
    }

    float* Cp = g_act2 + cOff;
    const int mr = lane >> 2, nc = (lane & 3) * 2;
#pragma unroll
    for (int mi = 0; mi < 4; mi++) {
#pragma unroll
        for (int ni = 0; ni < 4; ni++) {
            size_t row0 = (size_t)(ib + m0 + mi * 16 + mr) * NN + jb + n0 + ni * 8 + nc;
            *(float2*)(Cp + row0)          = make_float2(acc[mi][ni][0], acc[mi][ni][1]);
            *(float2*)(Cp + row0 + 8 * NN) = make_float2(acc[mi][ni][2], acc[mi][ni][3]);
        }
    }
}

// ---------------------------------------------------------------------------
// K4: channel-norm stats (mean/var over c=128) per (i,j).
// ---------------------------------------------------------------------------
__global__ void k_cstats() {
    size_t r = (size_t)blockIdx.x * 256 + threadIdx.x;
    float s = 0.0f, q = 0.0f;
#pragma unroll 8
    for (int c = 0; c < CC; c++) {
        float v = g_act2[(size_t)c * RR + r];
        s += v;
        q += v * v;
    }
    float m = s * (1.0f / CC);
    float var = q * (1.0f / CC) - m * m;
    g_mean[r] = m;
    g_rstd[r] = rsqrtf(var + 1e-5f);
}

// ---------------------------------------------------------------------------
// K5 (mma): dual GEMM on raw act2 (cs folded into w1) + x gate GEMM.
// Tile: 128 rows x 64 e. Single-stage smem, 4 K-chunks of 32.
// Epilogue: out = (rstd*(P - m*S1) + S2 + bout) * sigm(G + bgo).
// ---------------------------------------------------------------------------
#define FN_SMEM_BYTES 61440
// layout: a1h 0, a1l 10240, a2h 20480, a2l 30720, w1h 40960, w1l 46080,
//         w2h 51200, w2l 56320

__global__ void __launch_bounds__(256, 1) k_final_mma(const float* __restrict__ bout,
                                                      const float* __restrict__ bgo,
                                                      float* __restrict__ out) {
    extern __shared__ char smem[];
    const uint32_t sbase = smem_u32(smem);
    const int t = threadIdx.x, lane = t & 31, wid = t >> 5;
    const int eb = blockIdx.x * 64;
    const size_t rb = (size_t)blockIdx.y * 128;
    const int m0 = (wid >> 2) * 64, n0 = (wid & 3) * 16;

    float accO[4][2][4] = {}, accG[4][2][4] = {};

    for (int kch = 0; kch < 4; kch++) {
        const int kc = kch * 32;
        // x tiles via cp.async
        {
            const __nv_bfloat16* xs[2] = {g_xh, g_xl};
#pragma unroll
            for (int arr = 0; arr < 2; arr++) {
                uint32_t tb = sbase + 20480 + arr * 10240;
#pragma unroll
                for (int it = 0; it < 2; it++) {
                    int idx = it * 256 + t;
                    int r = idx >> 2, ch = idx & 3;
                    cp_async16(tb + r * 80 + ch * 16, xs[arr] + (rb + r) * CC + kc + ch * 8);
                }
            }
        }
        // weight tiles via cp.async
        {
            const __nv_bfloat16* ws[4] = {g_w1h, g_w1l, g_w2h, g_w2l};
#pragma unroll
            for (int arr = 0; arr < 4; arr++) {
                uint32_t tb = sbase + 40960 + arr * 5120;
                int e = t >> 2, ch = t & 3;
                cp_async16(tb + e * 80 + ch * 16, ws[arr] + (size_t)(eb + e) * CC + kc + ch * 8);
            }
        }
        CP_COMMIT();
        // act2 LDG + convert to bf16 hi/lo into a1h/a1l
        {
            int cl = t >> 3, rblk = t & 7;     // 32 c x 8 r-blocks of 16
            const float* src = g_act2 + (size_t)(kc + cl) * RR + rb + rblk * 16;
#pragma unroll
            for (int q4 = 0; q4 < 4; q4++) {
                float4 v = *(const float4*)(src + q4 * 4);
                float vv[4] = {v.x, v.y, v.z, v.w};
#pragma unroll
                for (int j = 0; j < 4; j++) {
                    int r = rblk * 16 + q4 * 4 + j;
                    unsigned short h, l;
                    split_bf16(vv[j], h, l);
                    *(unsigned short*)(smem + r * 80 + cl * 2)         = h;
                    *(unsigned short*)(smem + 10240 + r * 80 + cl * 2) = l;
                }
            }
        }
        CP_WAIT0();
        __syncthreads();

        const uint32_t a1H = sbase + (m0 + (lane & 15)) * 80 + (lane >> 4) * 16;
        const uint32_t a1L = a1H + 10240;
        const uint32_t a2H = a1H + 20480;
        const uint32_t a2L = a1H + 30720;
        const uint32_t wb  = sbase + 40960 + (n0 + (lane & 7)) * 80 + ((lane >> 3) & 1) * 16;
#pragma unroll
        for (int kk = 0; kk < 2; kk++) {
            const uint32_t ko = kk * 32;
            uint32_t a1h[4][4], a1l[4][4], a2h[4][4], a2l[4][4];
            uint32_t b1h[2][2], b1l[2][2], b2h[2][2], b2l[2][2];
#pragma unroll
            for (int mi = 0; mi < 4; mi++) {
                ldsm4(a1H + mi * 1280 + ko, a1h[mi]);
                ldsm4(a1L + mi * 1280 + ko, a1l[mi]);
                ldsm4(a2H + mi * 1280 + ko, a2h[mi]);
                ldsm4(a2L + mi * 1280 + ko, a2l[mi]);
            }
#pragma unroll
            for (int ni = 0; ni < 2; ni++) {
                ldsm2(wb + ni * 640 + ko,          b1h[ni]);
                ldsm2(wb + ni * 640 + ko + 5120,   b1l[ni]);
                ldsm2(wb + ni * 640 + ko + 10240,  b2h[ni]);
                ldsm2(wb + ni * 640 + ko + 15360,  b2l[ni]);
            }
#pragma unroll
            for (int mi = 0; mi < 4; mi++)
#pragma unroll
                for (int ni = 0; ni < 2; ni++) {
                    mma16816(accO[mi][ni], a1h[mi], b1h[ni]);
                    mma16816(accO[mi][ni], a1h[mi], b1l[ni]);
                    mma16816(accO[mi][ni], a1l[mi], b1h[ni]);
                    mma16816(accG[mi][ni], a2h[mi], b2h[ni]);
                    mma16816(accG[mi][ni], a2h[mi], b2l[ni]);
                    mma16816(accG[mi][ni], a2l[mi], b2h[ni]);
                }
        }
        __syncthreads();
    }

    // Epilogue: affine channel-norm + bias + sigmoid gate, direct stores
    const int mr = lane >> 2, ncl = (lane & 3) * 2;
#pragma unroll
    for (int ni = 0; ni < 2; ni++) {
        int e0 = eb + n0 + ni * 8 + ncl;
        float s1a = g_S1[e0], s1b = g_S1[e0 + 1];
        float s2a = g_S2[e0], s2b = g_S2[e0 + 1];
        float boa = bout[e0], bob = bout[e0 + 1];
        float bga = bgo[e0], bgb = bgo[e0 + 1];
#pragma unroll
        for (int mi = 0; mi < 4; mi++) {
#pragma unroll
            for (int half = 0; half < 2; half++) {
                size_t r = rb + m0 + mi * 16 + mr + half * 8;
                float mm = g_mean[r], rs = g_rstd[r];
                float p0 = accO[mi][ni][half * 2], p1 = accO[mi][ni][half * 2 + 1];
                float q0 = accG[mi][ni][half * 2], q1 = accG[mi][ni][half * 2 + 1];
                float o0 = (rs * (p0 - mm * s1a) + s2a + boa) * sigm(q0 + bga);
                float o1 = (rs * (p1 - mm * s1b) + s2b + bob) * sigm(q1 + bgb);
                *(float2*)(out + r * CC + e0) = make_float2(o0, o1);
            }
        }
    }
}

// ---------------------------------------------------------------------------
extern "C" void kernel_launch(void* const* d_in, const int* in_sizes, int n_in,
                              void* d_out, int out_size) {
    const float* act   = (const float*)d_in[0];
    const float* mask  = (const float*)d_in[1];
    const float* ln_s  = (const float*)d_in[2];
    const float* ln_o  = (const float*)d_in[3];
    const float* wproj = (const float*)d_in[4];
    const float* wgate = (const float*)d_in[5];
    const float* cn_s  = (const float*)d_in[6];
    const float* cn_o  = (const float*)d_in[7];
    const float* wout  = (const float*)d_in[8];
    const float* bout  = (const float*)d_in[9];
    const float* wgo   = (const float*)d_in[10];
    const float* bgo   = (const float*)d_in[11];
    float* out = (float*)d_out;

    cudaFuncSetAttribute(k_projgate_mma, cudaFuncAttributeMaxDynamicSharedMemorySize, PG_SMEM_BYTES);
    cudaFuncSetAttribute(k_pairmm_mma, cudaFuncAttributeMaxDynamicSharedMemorySize, PM_SMEM_BYTES);
    cudaFuncSetAttribute(k_final_mma, cudaFuncAttributeMaxDynamicSharedMemorySize, FN_SMEM_BYTES);

    k_layernorm<<<(int)(RR / 8), 256>>>(act, ln_s, ln_o);
    k_prep_pg<<<128, 256>>>(wproj, wgate);
    k_prep_out<<<64, 256>>>(wout, wgo, cn_s);
    k_prep_s<<<1, 128>>>(wout, cn_s, cn_o);
    k_projgate_mma<<<dim3(4, (unsigned)(RR / 128)), 256, PG_SMEM_BYTES>>>(mask);
    k_pairmm_mma<<<dim3(4, 4, 128), 256, PM_SMEM_BYTES>>>();
    k_cstats<<<(int)(RR / 256), 256>>>();
    k_final_mma<<<dim3(2, (unsigned)(RR / 128)), 256, FN_SMEM_BYTES>>>(bout, bgo, out);
}

// round 5
// speedup vs baseline: 1.8255x; 1.1972x over previous
#include <cuda_runtime.h>
#include <cuda_bf16.h>
#include <math.h>
#include <cstdint>

#define NN 512
#define CC 128
constexpr size_t RR = (size_t)NN * NN;
constexpr size_t RC = RR * CC;

// Scratch
__device__ __nv_bfloat16 g_xh[RC], g_xl[RC];        // layernormed x, [r][c]
__device__ __nv_bfloat16 g_ah[RC], g_al[RC];        // a, [c][i][k]
__device__ __nv_bfloat16 g_bh[RC], g_bl[RC];        // b, [c][j][k]
__device__ __nv_bfloat16 g_a2h[RC], g_a2l[RC];      // act2, [c][i][j]
__device__ float g_mean[RR], g_rstd[RR];

// Prepped weights ([n][k], bf16 hi/lo)
__device__ __nv_bfloat16 g_wph[256 * CC], g_wpl[256 * CC];
__device__ __nv_bfloat16 g_wgh[256 * CC], g_wgl[256 * CC];
__device__ __nv_bfloat16 g_w1h[CC * CC], g_w1l[CC * CC];   // cs ⊙ w_out, transposed
__device__ __nv_bfloat16 g_w2h[CC * CC], g_w2l[CC * CC];   // w_gate_out, transposed
__device__ float g_S1[CC], g_S2[CC];

__device__ __forceinline__ float sigm(float z) { return 1.0f / (1.0f + __expf(-z)); }
__device__ __forceinline__ void split_bf16(float v, unsigned short& h, unsigned short& l) {
    __nv_bfloat16 hb = __float2bfloat16(v);
    float rem = v - __bfloat162float(hb);
    h = __bfloat16_as_ushort(hb);
    l = __bfloat16_as_ushort(__float2bfloat16(rem));
}
__device__ __forceinline__ float bf2f(uint32_t u) {
    return __bfloat162float(__ushort_as_bfloat16((unsigned short)(u & 0xffffu)));
}
__device__ __forceinline__ uint32_t smem_u32(const void* p) {
    uint32_t a;
    asm("{ .reg .u64 t; cvta.to.shared.u64 t, %1; cvt.u32.u64 %0, t; }" : "=r"(a) : "l"(p));
    return a;
}
__device__ __forceinline__ void cp_async16(uint32_t dst, const void* src) {
    asm volatile("cp.async.cg.shared.global [%0], [%1], 16;" :: "r"(dst), "l"(src));
}
#define CP_COMMIT() asm volatile("cp.async.commit_group;" ::: "memory")
#define CP_WAIT1()  asm volatile("cp.async.wait_group 1;" ::: "memory")

__device__ __forceinline__ void ldsm4(uint32_t addr, uint32_t* r) {
    asm volatile("ldmatrix.sync.aligned.m8n8.x4.shared.b16 {%0,%1,%2,%3}, [%4];"
                 : "=r"(r[0]), "=r"(r[1]), "=r"(r[2]), "=r"(r[3]) : "r"(addr));
}
__device__ __forceinline__ void ldsm4t(uint32_t addr, uint32_t* r) {
    asm volatile("ldmatrix.sync.aligned.m8n8.x4.trans.shared.b16 {%0,%1,%2,%3}, [%4];"
                 : "=r"(r[0]), "=r"(r[1]), "=r"(r[2]), "=r"(r[3]) : "r"(addr));
}
__device__ __forceinline__ void ldsm2(uint32_t addr, uint32_t* r) {
    asm volatile("ldmatrix.sync.aligned.m8n8.x2.shared.b16 {%0,%1}, [%2];"
                 : "=r"(r[0]), "=r"(r[1]) : "r"(addr));
}
__device__ __forceinline__ void mma16816(float* d, const uint32_t* a, const uint32_t* b) {
    asm volatile("mma.sync.aligned.m16n8k16.row.col.f32.bf16.bf16.f32 "
                 "{%0,%1,%2,%3}, {%4,%5,%6,%7}, {%8,%9}, {%0,%1,%2,%3};"
                 : "+f"(d[0]), "+f"(d[1]), "+f"(d[2]), "+f"(d[3])
                 : "r"(a[0]), "r"(a[1]), "r"(a[2]), "r"(a[3]), "r"(b[0]), "r"(b[1]));
}

// ---------------------------------------------------------------------------
// K: LayerNorm -> bf16 hi/lo x
// ---------------------------------------------------------------------------
__global__ void k_layernorm(const float* __restrict__ act,
                            const float* __restrict__ scale,
                            const float* __restrict__ offset) {
    int warp = threadIdx.x >> 5, lane = threadIdx.x & 31;
    size_t row = (size_t)blockIdx.x * 8 + warp;
    float4 v = ((const float4*)(act + row * CC))[lane];
    float s = v.x + v.y + v.z + v.w;
    float q = v.x * v.x + v.y * v.y + v.z * v.z + v.w * v.w;
#pragma unroll
    for (int o = 16; o; o >>= 1) {
        s += __shfl_xor_sync(0xffffffffu, s, o);
        q += __shfl_xor_sync(0xffffffffu, q, o);
    }
    float m = s * (1.0f / CC);
    float rs = rsqrtf(q * (1.0f / CC) - m * m + 1e-5f);
    float4 sc = ((const float4*)scale)[lane];
    float4 of = ((const float4*)offset)[lane];
    float o[4] = {(v.x - m) * rs * sc.x + of.x, (v.y - m) * rs * sc.y + of.y,
                  (v.z - m) * rs * sc.z + of.z, (v.w - m) * rs * sc.w + of.w};
    unsigned short hs[4], ls[4];
#pragma unroll
    for (int u = 0; u < 4; u++) split_bf16(o[u], hs[u], ls[u]);
    *(uint2*)(g_xh + row * CC + lane * 4) =
        make_uint2((uint32_t)hs[0] | ((uint32_t)hs[1] << 16), (uint32_t)hs[2] | ((uint32_t)hs[3] << 16));
    *(uint2*)(g_xl + row * CC + lane * 4) =
        make_uint2((uint32_t)ls[0] | ((uint32_t)ls[1] << 16), (uint32_t)ls[2] | ((uint32_t)ls[3] << 16));
}

// ---------------------------------------------------------------------------
// Weight prep
// ---------------------------------------------------------------------------
__global__ void k_prep_pg(const float* __restrict__ wproj, const float* __restrict__ wgate) {
    int idx = blockIdx.x * 256 + threadIdx.x;
    int d = idx >> 7, c = idx & 127;
    unsigned short h, l;
    split_bf16(wproj[(size_t)c * 256 + d], h, l);
    g_wph[idx] = __ushort_as_bfloat16(h); g_wpl[idx] = __ushort_as_bfloat16(l);
    split_bf16(wgate[(size_t)c * 256 + d], h, l);
    g_wgh[idx] = __ushort_as_bfloat16(h); g_wgl[idx] = __ushort_as_bfloat16(l);
}
__global__ void k_prep_out(const float* __restrict__ wout, const float* __restrict__ wgo,
                           const float* __restrict__ cs) {
    int idx = blockIdx.x * 256 + threadIdx.x;
    int e = idx >> 7, c = idx & 127;
    unsigned short h, l;
    split_bf16(cs[c] * wout[(size_t)c * CC + e], h, l);
    g_w1h[idx] = __ushort_as_bfloat16(h); g_w1l[idx] = __ushort_as_bfloat16(l);
    split_bf16(wgo[(size_t)c * CC + e], h, l);
    g_w2h[idx] = __ushort_as_bfloat16(h); g_w2l[idx] = __ushort_as_bfloat16(l);
}
__global__ void k_prep_s(const float* __restrict__ wout,
                         const float* __restrict__ cs, const float* __restrict__ co) {
    int e = blockIdx.x, c = threadIdx.x;      // 128 blocks x 128 threads
    float w = wout[(size_t)c * CC + e];
    float s1 = cs[c] * w, s2 = co[c] * w;
    __shared__ float r1[4], r2[4];
#pragma unroll
    for (int o = 16; o; o >>= 1) {
        s1 += __shfl_xor_sync(0xffffffffu, s1, o);
        s2 += __shfl_xor_sync(0xffffffffu, s2, o);
    }
    if ((c & 31) == 0) { r1[c >> 5] = s1; r2[c >> 5] = s2; }
    __syncthreads();
    if (c == 0) {
        g_S1[e] = r1[0] + r1[1] + r1[2] + r1[3];
        g_S2[e] = r2[0] + r2[1] + r2[2] + r2[3];
    }
}

// ---------------------------------------------------------------------------
// K projgate (mma): 128r x 128d dual-GEMM, K=128 (4 chunks), 2-stage.
// Epilogue fused in registers: val = P * sigm(G) * mask, transpose via smem,
// scatter bf16 hi/lo into pair layout.
// ---------------------------------------------------------------------------
#define PG_STAGE 61440
#define PG_SMEM  (2 * PG_STAGE)

__device__ __forceinline__ void pg_load(uint32_t sb, int kc, size_t rb, int db, int t) {
    const __nv_bfloat16* xs[2] = {g_xh, g_xl};
#pragma unroll
    for (int a = 0; a < 2; a++) {
        uint32_t tb = sb + a * 10240;
#pragma unroll
        for (int it = 0; it < 2; it++) {
            int idx = it * 256 + t;
            int r = idx >> 2, ch = idx & 3;
            cp_async16(tb + r * 80 + ch * 16, xs[a] + (rb + r) * CC + kc + ch * 8);
        }
    }
    const __nv_bfloat16* ws[4] = {g_wph, g_wpl, g_wgh, g_wgl};
#pragma unroll
    for (int a = 0; a < 4; a++) {
        uint32_t tb = sb + 20480 + a * 10240;
#pragma unroll
        for (int it = 0; it < 2; it++) {
            int idx = it * 256 + t;
            int d = idx >> 2, ch = idx & 3;
            cp_async16(tb + d * 80 + ch * 16, ws[a] + (size_t)(db + d) * CC + kc + ch * 8);
        }
    }
}

__global__ void __launch_bounds__(256, 1) k_projgate_mma(const float* __restrict__ mask) {
    extern __shared__ char smem[];
    const uint32_t sbase = smem_u32(smem);
    const int t = threadIdx.x, lane = t & 31, wid = t >> 5;
    const int db = blockIdx.x * 128;
    const size_t rb = (size_t)blockIdx.y * 128;
    const int m0 = (wid >> 2) * 64, n0 = (wid & 3) * 32;

    float accP[4][4][4] = {}, accG[4][4][4] = {};

    pg_load(sbase, 0, rb, db, t);  CP_COMMIT();
    pg_load(sbase + PG_STAGE, 32, rb, db, t);  CP_COMMIT();

    for (int kch = 0; kch < 4; kch++) {
        CP_WAIT1();
        __syncthreads();
        const uint32_t sb = sbase + (kch & 1) * PG_STAGE;
        const uint32_t aH = sb + (m0 + (lane & 15)) * 80 + (lane >> 4) * 16;
        const uint32_t wB = sb + 20480 + (n0 + (lane & 7)) * 80 + ((lane >> 3) & 1) * 16;
#pragma unroll
        for (int kk = 0; kk < 2; kk++) {
            const uint32_t ko = kk * 32;
            uint32_t ah[4][4], al[4][4];
#pragma unroll
            for (int mi = 0; mi < 4; mi++) {
                ldsm4(aH + mi * 1280 + ko, ah[mi]);
                ldsm4(aH + mi * 1280 + ko + 10240, al[mi]);
            }
#pragma unroll
            for (int ni = 0; ni < 4; ni++) {
                uint32_t bph[2], bpl[2], bgh[2], bgl[2];
                uint32_t wa = wB + ni * 640 + ko;
                ldsm2(wa, bph);
                ldsm2(wa + 10240, bpl);
                ldsm2(wa + 20480, bgh);
                ldsm2(wa + 30720, bgl);
#pragma unroll
                for (int mi = 0; mi < 4; mi++) {
                    mma16816(accP[mi][ni], ah[mi], bph);
                    mma16816(accP[mi][ni], ah[mi], bpl);
                    mma16816(accP[mi][ni], al[mi], bph);
                    mma16816(accG[mi][ni], ah[mi], bgh);
                    mma16816(accG[mi][ni], ah[mi], bgl);
                    mma16816(accG[mi][ni], al[mi], bgh);
                }
            }
        }
        __syncthreads();
        if (kch + 2 < 4) pg_load(sbase + (kch & 1) * PG_STAGE, (kch + 2) * 32, rb, db, t);
        CP_COMMIT();
    }

    // Fused epilogue: val in registers -> smem transpose [d][132r] -> scatter
    float* buf = (float*)smem;          // 128*132*4 = 67584 B
    const int mr = lane >> 2, ncq = lane & 3;
#pragma unroll
    for (int mi = 0; mi < 4; mi++) {
        int rl = m0 + mi * 16 + mr;
        float mk0 = __ldg(mask + rb + rl), mk8 = __ldg(mask + rb + rl + 8);
#pragma unroll
        for (int ni = 0; ni < 4; ni++) {
            int d0 = n0 + ni * 8 + ncq * 2;
            buf[d0 * 132 + rl]           = accP[mi][ni][0] * sigm(accG[mi][ni][0]) * mk0;
            buf[(d0 + 1) * 132 + rl]     = accP[mi][ni][1] * sigm(accG[mi][ni][1]) * mk0;
            buf[d0 * 132 + rl + 8]       = accP[mi][ni][2] * sigm(accG[mi][ni][2]) * mk8;
            buf[(d0 + 1) * 132 + rl + 8] = accP[mi][ni][3] * sigm(accG[mi][ni][3]) * mk8;
        }
    }
    __syncthreads();

#pragma unroll
    for (int pass = 0; pass < 2; pass++) {
        int dl = pass * 64 + (t >> 2), rg = t & 3;
        int dg = db + dl, c = dg >> 1;
        __nv_bfloat16* dsth = (dg & 1) ? g_bh : g_ah;
        __nv_bfloat16* dstl = (dg & 1) ? g_bl : g_al;
        size_t base = (size_t)c * RR + rb + rg * 32;
#pragma unroll
        for (int i4 = 0; i4 < 4; i4++) {
            float4 va = *(float4*)&buf[dl * 132 + rg * 32 + i4 * 8];
            float4 vb = *(float4*)&buf[dl * 132 + rg * 32 + i4 * 8 + 4];
            float vv[8] = {va.x, va.y, va.z, va.w, vb.x, vb.y, vb.z, vb.w};
            unsigned short hs[8], ls[8];
#pragma unroll
            for (int j = 0; j < 8; j++) split_bf16(vv[j], hs[j], ls[j]);
            *(uint4*)(dsth + base + i4 * 8) =
                make_uint4((uint32_t)hs[0] | ((uint32_t)hs[1] << 16), (uint32_t)hs[2] | ((uint32_t)hs[3] << 16),
                           (uint32_t)hs[4] | ((uint32_t)hs[5] << 16), (uint32_t)hs[6] | ((uint32_t)hs[7] << 16));
            *(uint4*)(dstl + base + i4 * 8) =
                make_uint4((uint32_t)ls[0] | ((uint32_t)ls[1] << 16), (uint32_t)ls[2] | ((uint32_t)ls[3] << 16),
                           (uint32_t)ls[4] | ((uint32_t)ls[5] << 16), (uint32_t)ls[6] | ((uint32_t)ls[7] << 16));
        }
    }
}

// ---------------------------------------------------------------------------
// K pairmm (mma): act2[c] = a[c] @ b[c]^T, epilogue writes bf16 hi/lo.
// ---------------------------------------------------------------------------
#define PM_TILE_B   10240
#define PM_STAGE_B  (4 * PM_TILE_B)
#define PM_SMEM     (2 * PM_STAGE_B)

__device__ __forceinline__ void pm_load(uint32_t sb, int kc, size_t cOff, int ib, int jb, int t) {
    const __nv_bfloat16* srcs[4] = {g_ah, g_al, g_bh, g_bl};
#pragma unroll
    for (int tile = 0; tile < 4; tile++) {
        const int rbv = (tile < 2) ? ib : jb;
        const __nv_bfloat16* src = srcs[tile] + cOff;
        const uint32_t tb = sb + tile * PM_TILE_B;
#pragma unroll
        for (int it = 0; it < 2; it++) {
            int idx = it * 256 + t;
            int r = idx >> 2, ch = idx & 3;
            cp_async16(tb + r * 80 + ch * 16, src + (size_t)(rbv + r) * NN + kc + ch * 8);
        }
    }
}

__global__ void __launch_bounds__(256, 1) k_pairmm_mma() {
    extern __shared__ char smem[];
    const uint32_t sbase = smem_u32(smem);
    const int t = threadIdx.x, lane = t & 31, wid = t >> 5;
    const int c = blockIdx.z;
    const int ib = blockIdx.y * 128, jb = blockIdx.x * 128;
    const size_t cOff = (size_t)c * RR;
    const int m0 = (wid >> 2) * 64, n0 = (wid & 3) * 32;

    float acc[4][4][4] = {};

    pm_load(sbase, 0, cOff, ib, jb, t);  CP_COMMIT();
    pm_load(sbase + PM_STAGE_B, 32, cOff, ib, jb, t);  CP_COMMIT();

    for (int kch = 0; kch < 16; kch++) {
        CP_WAIT1();
        __syncthreads();
        const uint32_t sb = sbase + (kch & 1) * PM_STAGE_B;
        const uint32_t aH = sb + (m0 + (lane & 15)) * 80 + (lane >> 4) * 16;
        const uint32_t bH = sb + 2 * PM_TILE_B + (n0 + (lane & 7)) * 80 + ((lane >> 3) & 1) * 16;
#pragma unroll
        for (int kk = 0; kk < 2; kk++) {
            const uint32_t ko = kk * 32;
            uint32_t ah[4][4], al[4][4], bh[4][2], bl[4][2];
#pragma unroll
            for (int mi = 0; mi < 4; mi++) {
                ldsm4(aH + mi * 1280 + ko, ah[mi]);
                ldsm4(aH + mi * 1280 + ko + PM_TILE_B, al[mi]);
            }
#pragma unroll
            for (int ni = 0; ni < 4; ni++) {
                ldsm2(bH + ni * 640 + ko, bh[ni]);
                ldsm2(bH + ni * 640 + ko + PM_TILE_B, bl[ni]);
            }
#pragma unroll
            for (int mi = 0; mi < 4; mi++)
#pragma unroll
                for (int ni = 0; ni < 4; ni++) {
                    mma16816(acc[mi][ni], ah[mi], bh[ni]);
                    mma16816(acc[mi][ni], ah[mi], bl[ni]);
                    mma16816(acc[mi][ni], al[mi], bh[ni]);
                }
        }
        __syncthreads();
        if (kch + 2 < 16) pm_load(sbase + (kch & 1) * PM_STAGE_B, (kch + 2) * 32, cOff, ib, jb, t);
        CP_COMMIT();
    }

    const int mr = lane >> 2, nc = (lane & 3) * 2;
#pragma unroll
    for (int mi = 0; mi < 4; mi++)
#pragma unroll
        for (int ni = 0; ni < 4; ni++) {
            size_t pos0 = cOff + (size_t)(ib + m0 + mi * 16 + mr) * NN + jb + n0 + ni * 8 + nc;
            size_t pos8 = pos0 + (size_t)8 * NN;
            unsigned short h0, l0, h1, l1;
            split_bf16(acc[mi][ni][0], h0, l0); split_bf16(acc[mi][ni][1], h1, l1);
            *(uint32_t*)(g_a2h + pos0) = (uint32_t)h0 | ((uint32_t)h1 << 16);
            *(uint32_t*)(g_a2l + pos0) = (uint32_t)l0 | ((uint32_t)l1 << 16);
            split_bf16(acc[mi][ni][2], h0, l0); split_bf16(acc[mi][ni][3], h1, l1);
            *(uint32_t*)(g_a2h + pos8) = (uint32_t)h0 | ((uint32_t)h1 << 16);
            *(uint32_t*)(g_a2l + pos8) = (uint32_t)l0 | ((uint32_t)l1 << 16);
        }
}

// ---------------------------------------------------------------------------
// K cstats: mean/var over c per (i,j), reading bf16 hi/lo act2.
// ---------------------------------------------------------------------------
__global__ void k_cstats() {
    size_t r0 = ((size_t)blockIdx.x * 256 + threadIdx.x) * 4;
    float s[4] = {}, q[4] = {};
#pragma unroll 4
    for (int c = 0; c < CC; c++) {
        uint2 hv = *(const uint2*)(g_a2h + (size_t)c * RR + r0);
        uint2 lv = *(const uint2*)(g_a2l + (size_t)c * RR + r0);
        float v[4] = {bf2f(hv.x) + bf2f(lv.x), bf2f(hv.x >> 16) + bf2f(lv.x >> 16),
                      bf2f(hv.y) + bf2f(lv.y), bf2f(hv.y >> 16) + bf2f(lv.y >> 16)};
#pragma unroll
        for (int j = 0; j < 4; j++) { s[j] += v[j]; q[j] += v[j] * v[j]; }
    }
    float4 mo, ro;
    float* mp = &mo.x; float* rp = &ro.x;
#pragma unroll
    for (int j = 0; j < 4; j++) {
        float m = s[j] * (1.0f / CC);
        mp[j] = m;
        rp[j] = rsqrtf(q[j] * (1.0f / CC) - m * m + 1e-5f);
    }
    *(float4*)(g_mean + r0) = mo;
    *(float4*)(g_rstd + r0) = ro;
}

// ---------------------------------------------------------------------------
// K final (mma): 128r x 128e dual GEMM, 2-stage pipeline.
// O-GEMM: A = act2 ([c][r] bf16, ldmatrix.trans), B = cs⊙w_out.
// G-GEMM: A = x ([r][c]), B = w_gate_out.
// Epilogue: out = (rstd*(O - m*S1) + S2 + bout) * sigm(G + bgo).
// ---------------------------------------------------------------------------
#define FN_STAGE 78848
#define FN_SMEM  (2 * FN_STAGE)
// stage offsets: a1h 0 (32x272), a1l 8704, xh 17408 (128x80), xl 27648,
//                w1h 37888, w1l 48128, w2h 58368, w2l 68608

__device__ __forceinline__ void fn_load(uint32_t sb, int kc, size_t rb, int t) {
    const __nv_bfloat16* a1s[2] = {g_a2h, g_a2l};
#pragma unroll
    for (int a = 0; a < 2; a++) {
        uint32_t tb = sb + a * 8704;
#pragma unroll
        for (int it = 0; it < 2; it++) {
            int idx = it * 256 + t;
            int cc2 = idx >> 4, ch = idx & 15;
            cp_async16(tb + cc2 * 272 + ch * 16, a1s[a] + (size_t)(kc + cc2) * RR + rb + ch * 8);
        }
    }
    const __nv_bfloat16* xs[2] = {g_xh, g_xl};
#pragma unroll
    for (int a = 0; a < 2; a++) {
        uint32_t tb = sb + 17408 + a * 10240;
#pragma unroll
        for (int it = 0; it < 2; it++) {
            int idx = it * 256 + t;
            int r = idx >> 2, ch = idx & 3;
            cp_async16(tb + r * 80 + ch * 16, xs[a] + (rb + r) * CC + kc + ch * 8);
        }
    }
    const __nv_bfloat16* ws[4] = {g_w1h, g_w1l, g_w2h, g_w2l};
#pragma unroll
    for (int a = 0; a < 4; a++) {
        uint32_t tb = sb + 37888 + a * 10240;
#pragma unroll
        for (int it = 0; it < 2; it++) {
            int idx = it * 256 + t;
            int e = idx >> 2, ch = idx & 3;
            cp_async16(tb + e * 80 + ch * 16, ws[a] + (size_t)e * CC + kc + ch * 8);
        }
    }
}

__global__ void __launch_bounds__(256, 1) k_final_mma(const float* __restrict__ bout,
                                                      const float* __restrict__ bgo,
                                                      float* __restrict__ out) {
    extern __shared__ char smem[];
    const uint32_t sbase = smem_u32(smem);
    const int t = threadIdx.x, lane = t & 31, wid = t >> 5;
    const size_t rb = (size_t)blockIdx.x * 128;
    const int m0 = (wid >> 2) * 64, n0 = (wid & 3) * 32;

    float accO[4][4][4] = {}, accG[4][4][4] = {};

    // trans-ldmatrix lane mapping (for A1 in [c][r] layout)
    const int crow = (lane & 7) + ((lane >> 4) & 1) * 8;
    const int r8 = ((lane >> 3) & 1) * 8;

    fn_load(sbase, 0, rb, t);  CP_COMMIT();
    fn_load(sbase + FN_STAGE, 32, rb, t);  CP_COMMIT();

    for (int kch = 0; kch < 4; kch++) {
        CP_WAIT1();
        __syncthreads();
        const uint32_t sb = sbase + (kch & 1) * FN_STAGE;
        const uint32_t aX = sb + 17408 + (m0 + (lane & 15)) * 80 + (lane >> 4) * 16;
        const uint32_t w1B = sb + 37888 + (n0 + (lane & 7)) * 80 + ((lane >> 3) & 1) * 16;
        const uint32_t w2B = w1B + 20480;
#pragma unroll
        for (int kk = 0; kk < 2; kk++) {
            const uint32_t ko = kk * 32;
            // --- O GEMM (A1 via trans) ---
            {
                uint32_t a1h[4][4], a1l[4][4];
                uint32_t aT = sb + (kk * 16 + crow) * 272 + (m0 + r8) * 2;
#pragma unroll
                for (int mi = 0; mi < 4; mi++) {
                    ldsm4t(aT + mi * 32, a1h[mi]);
                    ldsm4t(aT + mi * 32 + 8704, a1l[mi]);
                }
#pragma unroll
                for (int ni = 0; ni < 4; ni++) {
                    uint32_t b1h[2], b1l[2];
                    ldsm2(w1B + ni * 640 + ko, b1h);
                    ldsm2(w1B + ni * 640 + ko + 10240, b1l);
#pragma unroll
                    for (int mi = 0; mi < 4; mi++) {
                        mma16816(accO[mi][ni], a1h[mi], b1h);
                        mma16816(accO[mi][ni], a1h[mi], b1l);
                        mma16816(accO[mi][ni], a1l[mi], b1h);
                    }
                }
            }
            // --- G GEMM (x normal) ---
            {
                uint32_t a2h[4][4], a2l[4][4];
#pragma unroll
                for (int mi = 0; mi < 4; mi++) {
                    ldsm4(aX + mi * 1280 + ko, a2h[mi]);
                    ldsm4(aX + mi * 1280 + ko + 10240, a2l[mi]);
                }
#pragma unroll
                for (int ni = 0; ni < 4; ni++) {
                    uint32_t b2h[2], b2l[2];
                    ldsm2(w2B + ni * 640 + ko, b2h);
                    ldsm2(w2B + ni * 640 + ko + 10240, b2l);
#pragma unroll
                    for (int mi = 0; mi < 4; mi++) {
                        mma16816(accG[mi][ni], a2h[mi], b2h);
                        mma16816(accG[mi][ni], a2h[mi], b2l);
                        mma16816(accG[mi][ni], a2l[mi], b2h);
                    }
                }
            }
        }
        __syncthreads();
        if (kch + 2 < 4) fn_load(sbase + (kch & 1) * FN_STAGE, (kch + 2) * 32, rb, t);
        CP_COMMIT();
    }

    // Epilogue
    const int mr = lane >> 2, ncl = (lane & 3) * 2;
    float mm[4][2], rs[4][2];
#pragma unroll
    for (int mi = 0; mi < 4; mi++)
#pragma unroll
        for (int half = 0; half < 2; half++) {
            size_t r = rb + m0 + mi * 16 + mr + half * 8;
            mm[mi][half] = g_mean[r];
            rs[mi][half] = g_rstd[r];
        }
#pragma unroll
    for (int ni = 0; ni < 4; ni++) {
        int e0 = n0 + ni * 8 + ncl;
        float s1a = g_S1[e0], s1b = g_S1[e0 + 1];
        float s2a = g_S2[e0], s2b = g_S2[e0 + 1];
        float boa = __ldg(bout + e0), bob = __ldg(bout + e0 + 1);
        float bga = __ldg(bgo + e0), bgb = __ldg(bgo + e0 + 1);
#pragma unroll
        for (int mi = 0; mi < 4; mi++)
#pragma unroll
            for (int half = 0; half < 2; half++) {
                size_t r = rb + m0 + mi * 16 + mr + half * 8;
                float p0 = accO[mi][ni][half * 2], p1 = accO[mi][ni][half * 2 + 1];
                float q0 = accG[mi][ni][half * 2], q1 = accG[mi][ni][half * 2 + 1];
                float o0 = (rs[mi][half] * (p0 - mm[mi][half] * s1a) + s2a + boa) * sigm(q0 + bga);
                float o1 = (rs[mi][half] * (p1 - mm[mi][half] * s1b) + s2b + bob) * sigm(q1 + bgb);
                *(float2*)(out + r * CC + e0) = make_float2(o0, o1);
            }
    }
}

// ---------------------------------------------------------------------------
extern "C" void kernel_launch(void* const* d_in, const int* in_sizes, int n_in,
                              void* d_out, int out_size) {
    const float* act   = (const float*)d_in[0];
    const float* mask  = (const float*)d_in[1];
    const float* ln_s  = (const float*)d_in[2];
    const float* ln_o  = (const float*)d_in[3];
    const float* wproj = (const float*)d_in[4];
    const float* wgate = (const float*)d_in[5];
    const float* cn_s  = (const float*)d_in[6];
    const float* cn_o  = (const float*)d_in[7];
    const float* wout  = (const float*)d_in[8];
    const float* bout  = (const float*)d_in[9];
    const float* wgo   = (const float*)d_in[10];
    const float* bgo   = (const float*)d_in[11];
    float* out = (float*)d_out;

    cudaFuncSetAttribute(k_projgate_mma, cudaFuncAttributeMaxDynamicSharedMemorySize, PG_SMEM);
    cudaFuncSetAttribute(k_pairmm_mma, cudaFuncAttributeMaxDynamicSharedMemorySize, PM_SMEM);
    cudaFuncSetAttribute(k_final_mma, cudaFuncAttributeMaxDynamicSharedMemorySize, FN_SMEM);

    k_prep_pg<<<128, 256>>>(wproj, wgate);                                  // 1
    k_prep_out<<<64, 256>>>(wout, wgo, cn_s);                               // 2
    k_layernorm<<<(int)(RR / 8), 256>>>(act, ln_s, ln_o);                   // 3
    k_projgate_mma<<<dim3(2, (unsigned)(RR / 128)), 256, PG_SMEM>>>(mask);  // 4 <- profiled
    k_prep_s<<<128, 128>>>(wout, cn_s, cn_o);                               // 5
    k_pairmm_mma<<<dim3(4, 4, 128), 256, PM_SMEM>>>();                      // 6
    k_cstats<<<256, 256>>>();                                               // 7
    k_final_mma<<<(unsigned)(RR / 128), 256, FN_SMEM>>>(bout, bgo, out);    // 8
}